// round 1
// baseline (speedup 1.0000x reference)
#include <cuda_runtime.h>

// LocalExpansion: out[bh, n, k, d] = in[bh, shift_k(n), d] (zero-padded 7x7 window)
// B*H = 16, N = 48*48 = 2304, K = 49, D = 64 (=16 float4)
// Output = 462 MB fp32 -> pure HBM-write-bound. One thread per output float4.

#define HEIGHT 48
#define WIDTH  48
#define KH 7
#define KW 7
#define DVEC 16                       // 64 floats = 16 float4
#define NPIX (HEIGHT * WIDTH)         // 2304
#define KK (KH * KW)                  // 49

__global__ void __launch_bounds__(256) local_expand_kernel(
    const float4* __restrict__ in, float4* __restrict__ out, unsigned int total)
{
    unsigned int t = blockIdx.x * 256u + threadIdx.x;
    if (t >= total) return;

    // t = ((bh * NPIX + n) * KK + k) * DVEC + dv
    unsigned int dv = t & (DVEC - 1);
    unsigned int r  = t >> 4;          // (bh*NPIX + n)*KK + k
    unsigned int k  = r % KK;
    unsigned int p  = r / KK;          // bh*NPIX + n
    unsigned int n  = p % NPIX;
    unsigned int bh = p / NPIX;

    int y = (int)(n / WIDTH);
    int x = (int)(n % WIDTH);
    int i = (int)(k / KW);
    int j = (int)(k % KW);

    int sy = y + i - (KH - 1) / 2;
    int sx = x + j - (KW - 1) / 2;

    float4 v = make_float4(0.f, 0.f, 0.f, 0.f);
    if ((unsigned)sy < (unsigned)HEIGHT && (unsigned)sx < (unsigned)WIDTH) {
        v = in[((unsigned)bh * NPIX + (unsigned)(sy * WIDTH + sx)) * DVEC + dv];
    }
    out[t] = v;
}

extern "C" void kernel_launch(void* const* d_in, const int* in_sizes, int n_in,
                              void* d_out, int out_size)
{
    const float4* in = (const float4*)d_in[0];
    float4* out = (float4*)d_out;

    // out_size = 2*8*2304*49*64 floats; total float4 = out_size / 4
    unsigned int total = (unsigned int)(out_size / 4);
    unsigned int blocks = (total + 255u) / 256u;
    local_expand_kernel<<<blocks, 256>>>(in, out, total);
}

// round 2
// speedup vs baseline: 1.1607x; 1.1607x over previous
#include <cuda_runtime.h>

// LocalExpansion: out[bh, n, k, d] = in[bh, shift_k(n), d] (zero-padded 7x7 window)
// B*H = 16, N = 48*48 = 2304, K = 49, D = 64 floats (= 16 float4)
//
// One thread per (pixel p = bh*2304+n, channel-vec dv in [0,16)). The thread
// writes all 49 taps. All 49 load offsets and 49 store offsets are
// compile-time immediates relative to two base pointers, so the unrolled
// body is ~4 instructions per 16B store instead of ~27.

#define HEIGHT 48
#define WIDTH  48
#define NPIX   (HEIGHT * WIDTH)   // 2304
#define KK     49
#define DVEC   16                 // 64 floats = 16 float4

__global__ void __launch_bounds__(256) local_expand_kernel(
    const float4* __restrict__ in, float4* __restrict__ out, unsigned int nthreads)
{
    unsigned int t = blockIdx.x * 256u + threadIdx.x;
    if (t >= nthreads) return;

    unsigned int dv = t & (DVEC - 1);
    unsigned int p  = t >> 4;            // bh*NPIX + n
    unsigned int n  = p % NPIX;
    int y = (int)(n / WIDTH);
    int x = (int)(n % WIDTH);

    const float4* __restrict__ src = in  + (size_t)p * DVEC + dv;       // pixel p, vec dv
    float4*       __restrict__ dst = out + (size_t)p * (KK * DVEC) + dv;

    #pragma unroll
    for (int i = 0; i < 7; ++i) {
        const bool yok = (unsigned)(y + i - 3) < (unsigned)HEIGHT;
        #pragma unroll
        for (int j = 0; j < 7; ++j) {
            const bool ok = yok && ((unsigned)(x + j - 3) < (unsigned)WIDTH);
            float4 v = make_float4(0.f, 0.f, 0.f, 0.f);
            const int off = ((i - 3) * WIDTH + (j - 3)) * DVEC;   // compile-time
            if (ok) v = src[off];
            dst[(i * 7 + j) * DVEC] = v;
        }
    }
}

extern "C" void kernel_launch(void* const* d_in, const int* in_sizes, int n_in,
                              void* d_out, int out_size)
{
    const float4* in = (const float4*)d_in[0];
    float4* out = (float4*)d_out;

    // out_size floats = 16*2304*49*64 ; threads = out floats / (4 * 49)
    unsigned int nthreads = (unsigned int)(out_size / (4 * KK));   // 589824
    unsigned int blocks = (nthreads + 255u) / 256u;                // 2304
    local_expand_kernel<<<blocks, 256>>>(in, out, nthreads);
}

// round 3
// speedup vs baseline: 1.2632x; 1.0883x over previous
#include <cuda_runtime.h>

// LocalExpansion via scatter: out[q, k, dv] = in[q + shift(k), dv], zero-padded.
// Inverted: thread (s, dv) loads v = in[s, dv] ONCE, then scatters v to the 49
// destinations q = s - shift(k) (predicated on q in-image), and writes zeros to
// its OWN row's taps whose source is out-of-bounds. Coverage is exact and
// disjoint. All 49+49 store offsets are compile-time immediates, stores are
// fire-and-forget (only one load on the scoreboard).
//
// B*H = 16, N = 48*48 = 2304, K = 49, D = 64 floats (= 16 float4)

#define HEIGHT 48
#define WIDTH  48
#define NPIX   (HEIGHT * WIDTH)   // 2304
#define KK     49
#define DVEC   16                 // 64 floats = 16 float4
#define ROWV   (KK * DVEC)        // 784 float4 per output pixel row

__global__ void __launch_bounds__(256) local_scatter_kernel(
    const float4* __restrict__ in, float4* __restrict__ out, unsigned int nthreads)
{
    unsigned int t = blockIdx.x * 256u + threadIdx.x;
    if (t >= nthreads) return;

    unsigned int dv = t & (DVEC - 1);
    unsigned int p  = t >> 4;            // bh*NPIX + s
    unsigned int n  = p % NPIX;
    int y = (int)(n / WIDTH);
    int x = (int)(n % WIDTH);

    const float4 v = __ldg(in + (size_t)p * DVEC + dv);   // single load
    float4* __restrict__ base = out + (size_t)p * ROWV + dv;
    const float4 z = make_float4(0.f, 0.f, 0.f, 0.f);

    #pragma unroll
    for (int i = 0; i < 7; ++i) {
        const bool src_yok = (unsigned)(y + (i - 3)) < (unsigned)HEIGHT;
        const bool dst_yok = (unsigned)(y - (i - 3)) < (unsigned)HEIGHT;
        #pragma unroll
        for (int j = 0; j < 7; ++j) {
            const int k = i * 7 + j;
            const bool dst_ok = dst_yok && ((unsigned)(x - (j - 3)) < (unsigned)WIDTH);
            const bool src_ok = src_yok && ((unsigned)(x + (j - 3)) < (unsigned)WIDTH);

            // scatter my value to pixel q = p - shift(k), tap k  (immediate offset)
            const int scat_off = -(((i - 3) * WIDTH) + (j - 3)) * ROWV + k * DVEC;
            if (dst_ok) __stcs(base + scat_off, v);
            // zero-fill my own row's tap k if its source is out of bounds
            if (!src_ok) __stcs(base + k * DVEC, z);
        }
    }
}

extern "C" void kernel_launch(void* const* d_in, const int* in_sizes, int n_in,
                              void* d_out, int out_size)
{
    const float4* in = (const float4*)d_in[0];
    float4* out = (float4*)d_out;

    // out floats = 16*2304*49*64 ; threads = (out floats) / (4 * 49) = 589824
    unsigned int nthreads = (unsigned int)(out_size / (4 * KK));
    unsigned int blocks = (nthreads + 255u) / 256u;   // 2304
    local_scatter_kernel<<<blocks, 256>>>(in, out, nthreads);
}